// round 8
// baseline (speedup 1.0000x reference)
#include <cuda_runtime.h>
#include <cstdint>

// NonLocalBlock: B=8, C=512, H=W=64 -> N=4096, CR=128
//   proj  = w_in[384,512] @ x[b,512,4096]   (tf32 TC)                -> Q,K,G
//   attn  = flash softmax(Q K^T) G          (tf32 TC, reg-staged)    -> Y
//   out   = x + w_out[512,128] @ Y^T        (tf32 TC)                -> out

#define BATCH 8
#define CIN   512
#define NTOK  4096
#define CRD   128

__device__ float g_q[(size_t)BATCH * NTOK * CRD];
__device__ float g_k[(size_t)BATCH * NTOK * CRD];
__device__ float g_g[(size_t)BATCH * NTOK * CRD];
__device__ float g_y[(size_t)BATCH * NTOK * CRD];

// ---------------------------------------------------------------------------
// tf32 mma.sync m16n8k8 (validated fragment layout, R3/R5).
// ---------------------------------------------------------------------------
__device__ __forceinline__ void mma_tf32(float d[4], const uint32_t a[4],
                                         uint32_t b0, uint32_t b1,
                                         const float c[4]) {
    asm volatile(
        "mma.sync.aligned.m16n8k8.row.col.f32.tf32.tf32.f32 "
        "{%0,%1,%2,%3}, {%4,%5,%6,%7}, {%8,%9}, {%10,%11,%12,%13};\n"
        : "=f"(d[0]), "=f"(d[1]), "=f"(d[2]), "=f"(d[3])
        : "r"(a[0]), "r"(a[1]), "r"(a[2]), "r"(a[3]),
          "r"(b0), "r"(b1),
          "f"(c[0]), "f"(c[1]), "f"(c[2]), "f"(c[3]));
}

// ---------------------------------------------------------------------------
// Kernel 1: projection GEMM on tensor cores (R5-validated, 93us).
// ---------------------------------------------------------------------------
#define XS_S 136
#define WJ_S 36

__global__ __launch_bounds__(256) void proj_tc_kernel(const float* __restrict__ x,
                                                      const float* __restrict__ w_in) {
    __shared__ float Xs[32 * XS_S];   // [c][token]
    __shared__ float Ws[128 * WJ_S];  // [j][c]
    const int n0 = blockIdx.x * 128;
    const int j0 = blockIdx.y * 128;
    const int b  = blockIdx.z;
    const int tid  = threadIdx.x;
    const int w    = tid >> 5;
    const int lane = tid & 31;
    const int gp = lane >> 2, tg = lane & 3;
    const int wm = w & 3;
    const int wn = w >> 2;

    const float* xb = x + (size_t)b * CIN * NTOK + n0;
    const float* wb = w_in + (size_t)j0 * CIN;

    float acc[2][8][4];
#pragma unroll
    for (int mt = 0; mt < 2; mt++)
#pragma unroll
        for (int nt = 0; nt < 8; nt++)
#pragma unroll
            for (int e = 0; e < 4; e++) acc[mt][nt][e] = 0.f;

    for (int c0 = 0; c0 < CIN; c0 += 32) {
        __syncthreads();
#pragma unroll
        for (int i = 0; i < 4; i++) {
            int idx = i * 256 + tid;
            int r = idx >> 5, c4 = (idx & 31) << 2;
            *(float4*)&Xs[r * XS_S + c4] =
                *(const float4*)(xb + (size_t)(c0 + r) * NTOK + c4);
        }
#pragma unroll
        for (int i = 0; i < 4; i++) {
            int idx = i * 256 + tid;
            int j = idx >> 3, f4 = (idx & 7) << 2;
            *(float4*)&Ws[j * WJ_S + f4] =
                *(const float4*)(wb + (size_t)j * CIN + c0 + f4);
        }
        __syncthreads();

#pragma unroll
        for (int kk = 0; kk < 4; kk++) {
            uint32_t a[2][4];
#pragma unroll
            for (int mt = 0; mt < 2; mt++) {
                int m = wm * 32 + mt * 16;
                a[mt][0] = __float_as_uint(Xs[(kk * 8 + tg) * XS_S + m + gp]);
                a[mt][1] = __float_as_uint(Xs[(kk * 8 + tg) * XS_S + m + gp + 8]);
                a[mt][2] = __float_as_uint(Xs[(kk * 8 + tg + 4) * XS_S + m + gp]);
                a[mt][3] = __float_as_uint(Xs[(kk * 8 + tg + 4) * XS_S + m + gp + 8]);
            }
#pragma unroll
            for (int nt = 0; nt < 8; nt++) {
                int j = wn * 64 + nt * 8;
                uint32_t b0 = __float_as_uint(Ws[(j + gp) * WJ_S + kk * 8 + tg]);
                uint32_t b1 = __float_as_uint(Ws[(j + gp) * WJ_S + kk * 8 + tg + 4]);
                mma_tf32(acc[0][nt], a[0], b0, b1, acc[0][nt]);
                mma_tf32(acc[1][nt], a[1], b0, b1, acc[1][nt]);
            }
        }
    }

    float* dst = (j0 == 0) ? g_q : (j0 == 128) ? g_k : g_g;
    float* base = dst + ((size_t)b * NTOK + n0 + wm * 32) * CRD + wn * 64;
#pragma unroll
    for (int mt = 0; mt < 2; mt++)
#pragma unroll
        for (int nt = 0; nt < 8; nt++) {
            *(float2*)&base[(mt * 16 + gp) * CRD + nt * 8 + 2 * tg] =
                make_float2(acc[mt][nt][0], acc[mt][nt][1]);
            *(float2*)&base[(mt * 16 + gp + 8) * CRD + nt * 8 + 2 * tg] =
                make_float2(acc[mt][nt][2], acc[mt][nt][3]);
        }
}

// ---------------------------------------------------------------------------
// Kernel 2: flash attention, tf32 TC, register-staged LDG prefetch +
// double-buffered smem, ONE block barrier per kv-tile.
// Per iter: LDG K(kt+1)->rS | GEMM1(Ks cur) | STS rS->Ks nxt |
//           LDG G(kt+1)->rS | softmax, GEMM2(Gs cur) | STS rS->Gs nxt | bar.
// dyn smem: 2*Ks[64][132] + 2*Gs[64][136] + Ps[8][16][68] = 172,032 B.
// ---------------------------------------------------------------------------
#define KS_STRIDE 132
#define GS_STRIDE 136
#define PS_STRIDE 68
#define KS_TILE (64 * KS_STRIDE)
#define GS_TILE (64 * GS_STRIDE)
#define ATTN_SMEM ((2 * KS_TILE + 2 * GS_TILE + 8 * 16 * PS_STRIDE) * 4)

__global__ __launch_bounds__(256, 1) void attn_tc_kernel() {
    extern __shared__ float smf[];
    float* KsB[2] = {smf, smf + KS_TILE};
    float* GsB[2] = {smf + 2 * KS_TILE, smf + 2 * KS_TILE + GS_TILE};
    float* Ps = smf + 2 * KS_TILE + 2 * GS_TILE;

    const int q0  = blockIdx.x * 128;
    const int b   = blockIdx.y;
    const int tid = threadIdx.x;
    const int w    = tid >> 5;
    const int lane = tid & 31;
    const int gp = lane >> 2;
    const int tg = lane & 3;

    // Per-thread staging coordinates (8 float4 slices of a 64x128 tile).
    int srow[8], scol[8];
#pragma unroll
    for (int i = 0; i < 8; i++) {
        int idx = i * 256 + tid;
        srow[i] = idx >> 5;
        scol[i] = (idx & 31) << 2;
    }

    const float* Kg = g_k + (size_t)b * NTOK * CRD;
    const float* Gg = g_g + (size_t)b * NTOK * CRD;

    float4 rS[8];

    // Prologue: stage tile 0 into buffer 0 (latency exposed once).
#pragma unroll
    for (int i = 0; i < 8; i++)
        rS[i] = *(const float4*)(Kg + (size_t)srow[i] * CRD + scol[i]);
#pragma unroll
    for (int i = 0; i < 8; i++)
        *(float4*)(KsB[0] + srow[i] * KS_STRIDE + scol[i]) = rS[i];
#pragma unroll
    for (int i = 0; i < 8; i++)
        rS[i] = *(const float4*)(Gg + (size_t)srow[i] * CRD + scol[i]);
#pragma unroll
    for (int i = 0; i < 8; i++)
        *(float4*)(GsB[0] + srow[i] * GS_STRIDE + scol[i]) = rS[i];

    // Q fragments in registers.
    const float* Qg = g_q + ((size_t)b * NTOK + q0 + w * 16) * CRD;
    uint32_t qf[16][4];
#pragma unroll
    for (int t = 0; t < 16; t++) {
        qf[t][0] = __float_as_uint(Qg[gp * CRD + t * 8 + tg]);
        qf[t][1] = __float_as_uint(Qg[(gp + 8) * CRD + t * 8 + tg]);
        qf[t][2] = __float_as_uint(Qg[gp * CRD + t * 8 + tg + 4]);
        qf[t][3] = __float_as_uint(Qg[(gp + 8) * CRD + t * 8 + tg + 4]);
    }

    float o[16][4];
#pragma unroll
    for (int j = 0; j < 16; j++)
#pragma unroll
        for (int e = 0; e < 4; e++) o[j][e] = 0.f;
    float m0 = -3.0e38f, m1 = -3.0e38f, l0 = 0.f, l1 = 0.f;

    float* Pw = Ps + w * 16 * PS_STRIDE;
    __syncthreads();   // tile 0 visible

    for (int kt = 0; kt < NTOK / 64; kt++) {
        const float* Ks = KsB[kt & 1];
        const float* Gs = GsB[kt & 1];
        float* Kn = KsB[(kt + 1) & 1];
        float* Gn = GsB[(kt + 1) & 1];
        const bool pre = (kt + 1 < NTOK / 64);
        const float* Kt1 = Kg + (size_t)(kt + 1) * 64 * CRD;
        const float* Gt1 = Gg + (size_t)(kt + 1) * 64 * CRD;

        // Prefetch next K tile into registers (consumed after GEMM1).
        if (pre) {
#pragma unroll
            for (int i = 0; i < 8; i++)
                rS[i] = *(const float4*)(Kt1 + (size_t)srow[i] * CRD + scol[i]);
        }

        // GEMM1: S[16q x 64kv] = Q x K^T
        float s[8][4];
#pragma unroll
        for (int j = 0; j < 8; j++)
#pragma unroll
            for (int e = 0; e < 4; e++) s[j][e] = 0.f;
#pragma unroll
        for (int t = 0; t < 16; t++) {
#pragma unroll
            for (int j = 0; j < 8; j++) {
                uint32_t b0 = __float_as_uint(
                    Ks[(j * 8 + gp) * KS_STRIDE + t * 8 + tg]);
                uint32_t b1 = __float_as_uint(
                    Ks[(j * 8 + gp) * KS_STRIDE + t * 8 + tg + 4]);
                mma_tf32(s[j], qf[t], b0, b1, s[j]);
            }
        }

        // Drain staged K into the other buffer; start G prefetch.
        if (pre) {
#pragma unroll
            for (int i = 0; i < 8; i++)
                *(float4*)(Kn + srow[i] * KS_STRIDE + scol[i]) = rS[i];
#pragma unroll
            for (int i = 0; i < 8; i++)
                rS[i] = *(const float4*)(Gt1 + (size_t)srow[i] * CRD + scol[i]);
        }

        // Online softmax (rows gp / gp+8, each across a 4-lane quad).
        float mx0 = -3.0e38f, mx1 = -3.0e38f;
#pragma unroll
        for (int j = 0; j < 8; j++) {
            mx0 = fmaxf(mx0, fmaxf(s[j][0], s[j][1]));
            mx1 = fmaxf(mx1, fmaxf(s[j][2], s[j][3]));
        }
        mx0 = fmaxf(mx0, __shfl_xor_sync(0xffffffffu, mx0, 1));
        mx0 = fmaxf(mx0, __shfl_xor_sync(0xffffffffu, mx0, 2));
        mx1 = fmaxf(mx1, __shfl_xor_sync(0xffffffffu, mx1, 1));
        mx1 = fmaxf(mx1, __shfl_xor_sync(0xffffffffu, mx1, 2));
        float nm0 = fmaxf(m0, mx0), nm1 = fmaxf(m1, mx1);
        float corr0 = __expf(m0 - nm0), corr1 = __expf(m1 - nm1);
        m0 = nm0; m1 = nm1;
        float ps0 = 0.f, ps1 = 0.f;
#pragma unroll
        for (int j = 0; j < 8; j++) {
            s[j][0] = __expf(s[j][0] - nm0);
            s[j][1] = __expf(s[j][1] - nm0);
            s[j][2] = __expf(s[j][2] - nm1);
            s[j][3] = __expf(s[j][3] - nm1);
            ps0 += s[j][0] + s[j][1];
            ps1 += s[j][2] + s[j][3];
        }
        ps0 += __shfl_xor_sync(0xffffffffu, ps0, 1);
        ps0 += __shfl_xor_sync(0xffffffffu, ps0, 2);
        ps1 += __shfl_xor_sync(0xffffffffu, ps1, 1);
        ps1 += __shfl_xor_sync(0xffffffffu, ps1, 2);
        l0 = l0 * corr0 + ps0;
        l1 = l1 * corr1 + ps1;
#pragma unroll
        for (int j = 0; j < 16; j++) {
            o[j][0] *= corr0; o[j][1] *= corr0;
            o[j][2] *= corr1; o[j][3] *= corr1;
        }

        // P -> warp-private smem (C-frag -> row-major).
#pragma unroll
        for (int j = 0; j < 8; j++) {
            *(float2*)&Pw[gp * PS_STRIDE + j * 8 + 2 * tg] =
                make_float2(s[j][0], s[j][1]);
            *(float2*)&Pw[(gp + 8) * PS_STRIDE + j * 8 + 2 * tg] =
                make_float2(s[j][2], s[j][3]);
        }
        __syncwarp();

        // GEMM2: O[16q x 128c] += P x G
#pragma unroll
        for (int ss = 0; ss < 8; ss++) {
            uint32_t a[4];
            a[0] = __float_as_uint(Pw[gp * PS_STRIDE + ss * 8 + tg]);
            a[1] = __float_as_uint(Pw[(gp + 8) * PS_STRIDE + ss * 8 + tg]);
            a[2] = __float_as_uint(Pw[gp * PS_STRIDE + ss * 8 + tg + 4]);
            a[3] = __float_as_uint(Pw[(gp + 8) * PS_STRIDE + ss * 8 + tg + 4]);
#pragma unroll
            for (int j2 = 0; j2 < 16; j2++) {
                uint32_t b0 = __float_as_uint(
                    Gs[(ss * 8 + tg) * GS_STRIDE + j2 * 8 + gp]);
                uint32_t b1 = __float_as_uint(
                    Gs[(ss * 8 + tg + 4) * GS_STRIDE + j2 * 8 + gp]);
                mma_tf32(o[j2], a, b0, b1, o[j2]);
            }
        }
        __syncwarp();   // P reads done before next iteration overwrites

        // Drain staged G into the other buffer.
        if (pre) {
#pragma unroll
            for (int i = 0; i < 8; i++)
                *(float4*)(Gn + srow[i] * GS_STRIDE + scol[i]) = rS[i];
        }
        __syncthreads();   // next tile fully staged + all readers done
    }

    const float inv0 = 1.f / l0, inv1 = 1.f / l1;
    float* Yg = g_y + ((size_t)b * NTOK + q0 + w * 16) * CRD;
#pragma unroll
    for (int j2 = 0; j2 < 16; j2++) {
        *(float2*)&Yg[gp * CRD + j2 * 8 + 2 * tg] =
            make_float2(o[j2][0] * inv0, o[j2][1] * inv0);
        *(float2*)&Yg[(gp + 8) * CRD + j2 * 8 + 2 * tg] =
            make_float2(o[j2][2] * inv1, o[j2][3] * inv1);
    }
}

// ---------------------------------------------------------------------------
// Kernel 3: output GEMM + residual on tensor cores (R5-validated).
// ---------------------------------------------------------------------------
#define OA_S 36

__global__ __launch_bounds__(256) void out_tc_kernel(const float* __restrict__ x,
                                                     const float* __restrict__ w_out,
                                                     float* __restrict__ out) {
    __shared__ float As[128 * OA_S];
    __shared__ float Bs[128 * OA_S];
    const int n0 = blockIdx.x * 128;
    const int c0 = blockIdx.y * 128;
    const int b  = blockIdx.z;
    const int tid  = threadIdx.x;
    const int w    = tid >> 5;
    const int lane = tid & 31;
    const int gp = lane >> 2, tg = lane & 3;
    const int wm = w & 3;
    const int wn = w >> 2;

    const float* Wg = w_out + (size_t)c0 * CRD;
    const float* Yg = g_y + ((size_t)b * NTOK + n0) * CRD;

    float acc[2][8][4];
#pragma unroll
    for (int mt = 0; mt < 2; mt++)
#pragma unroll
        for (int nt = 0; nt < 8; nt++)
#pragma unroll
            for (int e = 0; e < 4; e++) acc[mt][nt][e] = 0.f;

    for (int k0 = 0; k0 < CRD; k0 += 32) {
        __syncthreads();
#pragma unroll
        for (int i = 0; i < 4; i++) {
            int idx = i * 256 + tid;
            int r = idx >> 3, f4 = (idx & 7) << 2;
            *(float4*)&As[r * OA_S + f4] =
                *(const float4*)(Wg + (size_t)r * CRD + k0 + f4);
            *(float4*)&Bs[r * OA_S + f4] =
                *(const float4*)(Yg + (size_t)r * CRD + k0 + f4);
        }
        __syncthreads();

#pragma unroll
        for (int kk = 0; kk < 4; kk++) {
            uint32_t a[2][4];
#pragma unroll
            for (int mt = 0; mt < 2; mt++) {
                int c = wm * 32 + mt * 16;
                a[mt][0] = __float_as_uint(As[(c + gp) * OA_S + kk * 8 + tg]);
                a[mt][1] = __float_as_uint(As[(c + gp + 8) * OA_S + kk * 8 + tg]);
                a[mt][2] = __float_as_uint(As[(c + gp) * OA_S + kk * 8 + tg + 4]);
                a[mt][3] = __float_as_uint(As[(c + gp + 8) * OA_S + kk * 8 + tg + 4]);
            }
#pragma unroll
            for (int nt = 0; nt < 8; nt++) {
                int n = wn * 64 + nt * 8;
                uint32_t b0 = __float_as_uint(Bs[(n + gp) * OA_S + kk * 8 + tg]);
                uint32_t b1 = __float_as_uint(Bs[(n + gp) * OA_S + kk * 8 + tg + 4]);
                mma_tf32(acc[0][nt], a[0], b0, b1, acc[0][nt]);
                mma_tf32(acc[1][nt], a[1], b0, b1, acc[1][nt]);
            }
        }
    }

#pragma unroll
    for (int mt = 0; mt < 2; mt++)
#pragma unroll
        for (int nt = 0; nt < 8; nt++) {
            size_t r0 = ((size_t)b * CIN + c0 + wm * 32 + mt * 16 + gp) * NTOK
                        + n0 + wn * 64 + nt * 8 + 2 * tg;
            size_t r1 = r0 + (size_t)8 * NTOK;
            float2 x0 = *(const float2*)(x + r0);
            float2 x1 = *(const float2*)(x + r1);
            *(float2*)(out + r0) = make_float2(x0.x + acc[mt][nt][0],
                                               x0.y + acc[mt][nt][1]);
            *(float2*)(out + r1) = make_float2(x1.x + acc[mt][nt][2],
                                               x1.y + acc[mt][nt][3]);
        }
}

// ---------------------------------------------------------------------------
extern "C" void kernel_launch(void* const* d_in, const int* in_sizes, int n_in,
                              void* d_out, int out_size) {
    const float* x = nullptr; const float* w_in = nullptr; const float* w_out = nullptr;
    for (int i = 0; i < n_in; i++) {
        if (in_sizes[i] == BATCH * CIN * NTOK)      x     = (const float*)d_in[i];
        else if (in_sizes[i] == 3 * CRD * CIN)      w_in  = (const float*)d_in[i];
        else if (in_sizes[i] == CIN * CRD)          w_out = (const float*)d_in[i];
    }

    static int attr_done = 0;
    if (!attr_done) {
        cudaFuncSetAttribute(attn_tc_kernel,
                             cudaFuncAttributeMaxDynamicSharedMemorySize, ATTN_SMEM);
        cudaFuncSetAttribute(attn_tc_kernel,
                             cudaFuncAttributePreferredSharedMemoryCarveout, 100);
        attr_done = 1;
    }

    proj_tc_kernel<<<dim3(32, 3, 8), 256>>>(x, w_in);
    attn_tc_kernel<<<dim3(32, 8), 256, ATTN_SMEM>>>();
    out_tc_kernel<<<dim3(32, 4, 8), 256>>>(x, w_out, (float*)d_out);
}

// round 9
// speedup vs baseline: 1.8345x; 1.8345x over previous
#include <cuda_runtime.h>
#include <cuda_bf16.h>
#include <cstdint>

// NonLocalBlock: B=8, C=512, H=W=64 -> N=4096, CR=128
//   proj  = w_in[384,512] @ x[b,512,4096]   (tf32 TC)  -> Q,K,G [b,4096,128]
//   attn  = flash softmax(Q K^T) G          (bf16 TC)  -> Y     [b,4096,128]
//   out   = x + w_out[512,128] @ Y^T        (tf32 TC)  -> [b,512,4096]

#define BATCH 8
#define CIN   512
#define NTOK  4096
#define CRD   128

__device__ float g_q[(size_t)BATCH * NTOK * CRD];
__device__ float g_k[(size_t)BATCH * NTOK * CRD];
__device__ float g_g[(size_t)BATCH * NTOK * CRD];
__device__ float g_y[(size_t)BATCH * NTOK * CRD];

// ---------------------------------------------------------------------------
// tf32 mma.sync m16n8k8 (validated R3/R5 fragment layout).
// ---------------------------------------------------------------------------
__device__ __forceinline__ void mma_tf32(float d[4], const uint32_t a[4],
                                         uint32_t b0, uint32_t b1,
                                         const float c[4]) {
    asm volatile(
        "mma.sync.aligned.m16n8k8.row.col.f32.tf32.tf32.f32 "
        "{%0,%1,%2,%3}, {%4,%5,%6,%7}, {%8,%9}, {%10,%11,%12,%13};\n"
        : "=f"(d[0]), "=f"(d[1]), "=f"(d[2]), "=f"(d[3])
        : "r"(a[0]), "r"(a[1]), "r"(a[2]), "r"(a[3]),
          "r"(b0), "r"(b1),
          "f"(c[0]), "f"(c[1]), "f"(c[2]), "f"(c[3]));
}

// bf16 mma.sync m16n8k16.  A row-major (4 regs x bf16x2), B col-major
// (2 regs x bf16x2, low half = even k), C/D fp32.
__device__ __forceinline__ void mma_bf16(float d[4], const uint32_t a[4],
                                         uint32_t b0, uint32_t b1,
                                         const float c[4]) {
    asm volatile(
        "mma.sync.aligned.m16n8k16.row.col.f32.bf16.bf16.f32 "
        "{%0,%1,%2,%3}, {%4,%5,%6,%7}, {%8,%9}, {%10,%11,%12,%13};\n"
        : "=f"(d[0]), "=f"(d[1]), "=f"(d[2]), "=f"(d[3])
        : "r"(a[0]), "r"(a[1]), "r"(a[2]), "r"(a[3]),
          "r"(b0), "r"(b1),
          "f"(c[0]), "f"(c[1]), "f"(c[2]), "f"(c[3]));
}

__device__ __forceinline__ uint32_t packbf(float lo, float hi) {
    __nv_bfloat162 h = __floats2bfloat162_rn(lo, hi);  // lo -> .x (low bits)
    return *reinterpret_cast<uint32_t*>(&h);
}

// ---------------------------------------------------------------------------
// Kernel 1: projection GEMM, tf32 TC (R5-validated, 93us).
// ---------------------------------------------------------------------------
#define XS_S 136
#define WJ_S 36

__global__ __launch_bounds__(256) void proj_tc_kernel(const float* __restrict__ x,
                                                      const float* __restrict__ w_in) {
    __shared__ float Xs[32 * XS_S];
    __shared__ float Ws[128 * WJ_S];
    const int n0 = blockIdx.x * 128;
    const int j0 = blockIdx.y * 128;
    const int b  = blockIdx.z;
    const int tid  = threadIdx.x;
    const int w    = tid >> 5;
    const int lane = tid & 31;
    const int gp = lane >> 2, tg = lane & 3;
    const int wm = w & 3;
    const int wn = w >> 2;

    const float* xb = x + (size_t)b * CIN * NTOK + n0;
    const float* wb = w_in + (size_t)j0 * CIN;

    float acc[2][8][4];
#pragma unroll
    for (int mt = 0; mt < 2; mt++)
#pragma unroll
        for (int nt = 0; nt < 8; nt++)
#pragma unroll
            for (int e = 0; e < 4; e++) acc[mt][nt][e] = 0.f;

    for (int c0 = 0; c0 < CIN; c0 += 32) {
        __syncthreads();
#pragma unroll
        for (int i = 0; i < 4; i++) {
            int idx = i * 256 + tid;
            int r = idx >> 5, c4 = (idx & 31) << 2;
            *(float4*)&Xs[r * XS_S + c4] =
                *(const float4*)(xb + (size_t)(c0 + r) * NTOK + c4);
        }
#pragma unroll
        for (int i = 0; i < 4; i++) {
            int idx = i * 256 + tid;
            int j = idx >> 3, f4 = (idx & 7) << 2;
            *(float4*)&Ws[j * WJ_S + f4] =
                *(const float4*)(wb + (size_t)j * CIN + c0 + f4);
        }
        __syncthreads();

#pragma unroll
        for (int kk = 0; kk < 4; kk++) {
            uint32_t a[2][4];
#pragma unroll
            for (int mt = 0; mt < 2; mt++) {
                int m = wm * 32 + mt * 16;
                a[mt][0] = __float_as_uint(Xs[(kk * 8 + tg) * XS_S + m + gp]);
                a[mt][1] = __float_as_uint(Xs[(kk * 8 + tg) * XS_S + m + gp + 8]);
                a[mt][2] = __float_as_uint(Xs[(kk * 8 + tg + 4) * XS_S + m + gp]);
                a[mt][3] = __float_as_uint(Xs[(kk * 8 + tg + 4) * XS_S + m + gp + 8]);
            }
#pragma unroll
            for (int nt = 0; nt < 8; nt++) {
                int j = wn * 64 + nt * 8;
                uint32_t b0 = __float_as_uint(Ws[(j + gp) * WJ_S + kk * 8 + tg]);
                uint32_t b1 = __float_as_uint(Ws[(j + gp) * WJ_S + kk * 8 + tg + 4]);
                mma_tf32(acc[0][nt], a[0], b0, b1, acc[0][nt]);
                mma_tf32(acc[1][nt], a[1], b0, b1, acc[1][nt]);
            }
        }
    }

    float* dst = (j0 == 0) ? g_q : (j0 == 128) ? g_k : g_g;
    float* base = dst + ((size_t)b * NTOK + n0 + wm * 32) * CRD + wn * 64;
#pragma unroll
    for (int mt = 0; mt < 2; mt++)
#pragma unroll
        for (int nt = 0; nt < 8; nt++) {
            *(float2*)&base[(mt * 16 + gp) * CRD + nt * 8 + 2 * tg] =
                make_float2(acc[mt][nt][0], acc[mt][nt][1]);
            *(float2*)&base[(mt * 16 + gp + 8) * CRD + nt * 8 + 2 * tg] =
                make_float2(acc[mt][nt][2], acc[mt][nt][3]);
        }
}

// ---------------------------------------------------------------------------
// Kernel 2: flash attention, bf16 m16n8k16 tensor cores.
// CTA = 128 q-rows (8 warps x 16), kv tiles of 64, grid (32, 8), 256 thr.
// smem (static, 34.8 KB):
//   Ks32[64][68]  u32 = bf16x2 pairs along c   (GEMM1 B; banks 4gp+tg)
//   Gs32[32][136] u32 = bf16x2 pairs along kv  (GEMM2 B; banks 8tg+gp)
// P never touches smem: GEMM1 C-frag == GEMM2 A-frag for m16n8k16.
// ---------------------------------------------------------------------------
#define KS32_S 68
#define GS32_S 136

__global__ __launch_bounds__(256, 1) void attn_bf16_kernel() {
    __shared__ uint32_t Ks32[64 * KS32_S];
    __shared__ uint32_t Gs32[32 * GS32_S];

    const int q0  = blockIdx.x * 128;
    const int b   = blockIdx.y;
    const int tid = threadIdx.x;
    const int w    = tid >> 5;
    const int lane = tid & 31;
    const int gp = lane >> 2;
    const int tg = lane & 3;

    // Q fragments, packed bf16x2: 8 k-steps (of 16) x 4 regs.
    const float* Qg = g_q + ((size_t)b * NTOK + q0 + w * 16) * CRD;
    uint32_t qf[8][4];
#pragma unroll
    for (int t = 0; t < 8; t++) {
        float2 v;
        v = *(const float2*)(Qg + gp * CRD + t * 16 + 2 * tg);
        qf[t][0] = packbf(v.x, v.y);
        v = *(const float2*)(Qg + (gp + 8) * CRD + t * 16 + 2 * tg);
        qf[t][1] = packbf(v.x, v.y);
        v = *(const float2*)(Qg + gp * CRD + t * 16 + 8 + 2 * tg);
        qf[t][2] = packbf(v.x, v.y);
        v = *(const float2*)(Qg + (gp + 8) * CRD + t * 16 + 8 + 2 * tg);
        qf[t][3] = packbf(v.x, v.y);
    }

    float o[16][4];
#pragma unroll
    for (int j = 0; j < 16; j++)
#pragma unroll
        for (int e = 0; e < 4; e++) o[j][e] = 0.f;
    float m0 = -3.0e38f, m1 = -3.0e38f, l0 = 0.f, l1 = 0.f;

    const float* Kg = g_k + (size_t)b * NTOK * CRD;
    const float* Gg = g_g + (size_t)b * NTOK * CRD;

    for (int kt = 0; kt < NTOK / 64; kt++) {
        const float* Kt = Kg + (size_t)kt * 64 * CRD;
        const float* Gt = Gg + (size_t)kt * 64 * CRD;
        __syncthreads();   // previous tile's readers done

        // K tile: 64 rows x 128 fp32 -> 64 x 64 bf16x2 (pairs along c).
#pragma unroll
        for (int i = 0; i < 16; i++) {
            int idx = i * 256 + tid;          // 0..4095
            int r = idx >> 6, c32 = idx & 63;
            float2 v = *(const float2*)(Kt + r * CRD + 2 * c32);
            Ks32[r * KS32_S + c32] = packbf(v.x, v.y);
        }
        // G tile: pairs along kv: Gs32[kp][c] = {G[2kp][c], G[2kp+1][c]}.
#pragma unroll
        for (int i = 0; i < 8; i++) {
            int idx = i * 256 + tid;          // 0..2047
            int kp = idx >> 6, c2 = (idx & 63) << 1;
            float2 v0 = *(const float2*)(Gt + (2 * kp) * CRD + c2);
            float2 v1 = *(const float2*)(Gt + (2 * kp + 1) * CRD + c2);
            uint2 pk = make_uint2(packbf(v0.x, v1.x), packbf(v0.y, v1.y));
            *(uint2*)&Gs32[kp * GS32_S + c2] = pk;
        }
        __syncthreads();

        // GEMM1: S[16q x 64kv] = Q x K^T  (8 n-tiles, 8 k-steps of 16)
        float s[8][4];
#pragma unroll
        for (int j = 0; j < 8; j++)
#pragma unroll
            for (int e = 0; e < 4; e++) s[j][e] = 0.f;
#pragma unroll
        for (int t = 0; t < 8; t++) {
#pragma unroll
            for (int j = 0; j < 8; j++) {
                uint32_t b0 = Ks32[(j * 8 + gp) * KS32_S + t * 8 + tg];
                uint32_t b1 = Ks32[(j * 8 + gp) * KS32_S + t * 8 + tg + 4];
                mma_bf16(s[j], qf[t], b0, b1, s[j]);
            }
        }

        // Online softmax (rows gp / gp+8, each across a 4-lane quad).
        float mx0 = -3.0e38f, mx1 = -3.0e38f;
#pragma unroll
        for (int j = 0; j < 8; j++) {
            mx0 = fmaxf(mx0, fmaxf(s[j][0], s[j][1]));
            mx1 = fmaxf(mx1, fmaxf(s[j][2], s[j][3]));
        }
        mx0 = fmaxf(mx0, __shfl_xor_sync(0xffffffffu, mx0, 1));
        mx0 = fmaxf(mx0, __shfl_xor_sync(0xffffffffu, mx0, 2));
        mx1 = fmaxf(mx1, __shfl_xor_sync(0xffffffffu, mx1, 1));
        mx1 = fmaxf(mx1, __shfl_xor_sync(0xffffffffu, mx1, 2));
        float nm0 = fmaxf(m0, mx0), nm1 = fmaxf(m1, mx1);
        float corr0 = __expf(m0 - nm0), corr1 = __expf(m1 - nm1);
        m0 = nm0; m1 = nm1;
        float ps0 = 0.f, ps1 = 0.f;
#pragma unroll
        for (int j = 0; j < 8; j++) {
            s[j][0] = __expf(s[j][0] - nm0);
            s[j][1] = __expf(s[j][1] - nm0);
            s[j][2] = __expf(s[j][2] - nm1);
            s[j][3] = __expf(s[j][3] - nm1);
            ps0 += s[j][0] + s[j][1];
            ps1 += s[j][2] + s[j][3];
        }
        ps0 += __shfl_xor_sync(0xffffffffu, ps0, 1);
        ps0 += __shfl_xor_sync(0xffffffffu, ps0, 2);
        ps1 += __shfl_xor_sync(0xffffffffu, ps1, 1);
        ps1 += __shfl_xor_sync(0xffffffffu, ps1, 2);
        l0 = l0 * corr0 + ps0;
        l1 = l1 * corr1 + ps1;
#pragma unroll
        for (int j = 0; j < 16; j++) {
            o[j][0] *= corr0; o[j][1] *= corr0;
            o[j][2] *= corr1; o[j][3] *= corr1;
        }

        // Pack P into GEMM2 A-fragments IN REGISTERS (no smem, no syncwarp):
        // C-frag of GEMM1 (S[gp][8j+2tg..+1]) is exactly the m16n8k16 A-frag.
        uint32_t pe[8][2];
#pragma unroll
        for (int j = 0; j < 8; j++) {
            pe[j][0] = packbf(s[j][0], s[j][1]);   // row gp
            pe[j][1] = packbf(s[j][2], s[j][3]);   // row gp+8
        }

        // GEMM2: O[16q x 128c] += P x G  (4 k-steps of 16 kv, 16 n-tiles)
#pragma unroll
        for (int ss = 0; ss < 4; ss++) {
            uint32_t a[4] = {pe[2 * ss][0], pe[2 * ss][1],
                             pe[2 * ss + 1][0], pe[2 * ss + 1][1]};
#pragma unroll
            for (int j2 = 0; j2 < 16; j2++) {
                uint32_t b0 = Gs32[(ss * 8 + tg) * GS32_S + j2 * 8 + gp];
                uint32_t b1 = Gs32[(ss * 8 + tg + 4) * GS32_S + j2 * 8 + gp];
                mma_bf16(o[j2], a, b0, b1, o[j2]);
            }
        }
    }

    const float inv0 = 1.f / l0, inv1 = 1.f / l1;
    float* Yg = g_y + ((size_t)b * NTOK + q0 + w * 16) * CRD;
#pragma unroll
    for (int j2 = 0; j2 < 16; j2++) {
        *(float2*)&Yg[gp * CRD + j2 * 8 + 2 * tg] =
            make_float2(o[j2][0] * inv0, o[j2][1] * inv0);
        *(float2*)&Yg[(gp + 8) * CRD + j2 * 8 + 2 * tg] =
            make_float2(o[j2][2] * inv1, o[j2][3] * inv1);
    }
}

// ---------------------------------------------------------------------------
// Kernel 3: output GEMM + residual, tf32 TC (R5-validated).
// ---------------------------------------------------------------------------
#define OA_S 36

__global__ __launch_bounds__(256) void out_tc_kernel(const float* __restrict__ x,
                                                     const float* __restrict__ w_out,
                                                     float* __restrict__ out) {
    __shared__ float As[128 * OA_S];
    __shared__ float Bs[128 * OA_S];
    const int n0 = blockIdx.x * 128;
    const int c0 = blockIdx.y * 128;
    const int b  = blockIdx.z;
    const int tid  = threadIdx.x;
    const int w    = tid >> 5;
    const int lane = tid & 31;
    const int gp = lane >> 2, tg = lane & 3;
    const int wm = w & 3;
    const int wn = w >> 2;

    const float* Wg = w_out + (size_t)c0 * CRD;
    const float* Yg = g_y + ((size_t)b * NTOK + n0) * CRD;

    float acc[2][8][4];
#pragma unroll
    for (int mt = 0; mt < 2; mt++)
#pragma unroll
        for (int nt = 0; nt < 8; nt++)
#pragma unroll
            for (int e = 0; e < 4; e++) acc[mt][nt][e] = 0.f;

    for (int k0 = 0; k0 < CRD; k0 += 32) {
        __syncthreads();
#pragma unroll
        for (int i = 0; i < 4; i++) {
            int idx = i * 256 + tid;
            int r = idx >> 3, f4 = (idx & 7) << 2;
            *(float4*)&As[r * OA_S + f4] =
                *(const float4*)(Wg + (size_t)r * CRD + k0 + f4);
            *(float4*)&Bs[r * OA_S + f4] =
                *(const float4*)(Yg + (size_t)r * CRD + k0 + f4);
        }
        __syncthreads();

#pragma unroll
        for (int kk = 0; kk < 4; kk++) {
            uint32_t a[2][4];
#pragma unroll
            for (int mt = 0; mt < 2; mt++) {
                int c = wm * 32 + mt * 16;
                a[mt][0] = __float_as_uint(As[(c + gp) * OA_S + kk * 8 + tg]);
                a[mt][1] = __float_as_uint(As[(c + gp + 8) * OA_S + kk * 8 + tg]);
                a[mt][2] = __float_as_uint(As[(c + gp) * OA_S + kk * 8 + tg + 4]);
                a[mt][3] = __float_as_uint(As[(c + gp + 8) * OA_S + kk * 8 + tg + 4]);
            }
#pragma unroll
            for (int nt = 0; nt < 8; nt++) {
                int n = wn * 64 + nt * 8;
                uint32_t b0 = __float_as_uint(Bs[(n + gp) * OA_S + kk * 8 + tg]);
                uint32_t b1 = __float_as_uint(Bs[(n + gp) * OA_S + kk * 8 + tg + 4]);
                mma_tf32(acc[0][nt], a[0], b0, b1, acc[0][nt]);
                mma_tf32(acc[1][nt], a[1], b0, b1, acc[1][nt]);
            }
        }
    }

#pragma unroll
    for (int mt = 0; mt < 2; mt++)
#pragma unroll
        for (int nt = 0; nt < 8; nt++) {
            size_t r0 = ((size_t)b * CIN + c0 + wm * 32 + mt * 16 + gp) * NTOK
                        + n0 + wn * 64 + nt * 8 + 2 * tg;
            size_t r1 = r0 + (size_t)8 * NTOK;
            float2 x0 = *(const float2*)(x + r0);
            float2 x1 = *(const float2*)(x + r1);
            *(float2*)(out + r0) = make_float2(x0.x + acc[mt][nt][0],
                                               x0.y + acc[mt][nt][1]);
            *(float2*)(out + r1) = make_float2(x1.x + acc[mt][nt][2],
                                               x1.y + acc[mt][nt][3]);
        }
}

// ---------------------------------------------------------------------------
extern "C" void kernel_launch(void* const* d_in, const int* in_sizes, int n_in,
                              void* d_out, int out_size) {
    const float* x = nullptr; const float* w_in = nullptr; const float* w_out = nullptr;
    for (int i = 0; i < n_in; i++) {
        if (in_sizes[i] == BATCH * CIN * NTOK)      x     = (const float*)d_in[i];
        else if (in_sizes[i] == 3 * CRD * CIN)      w_in  = (const float*)d_in[i];
        else if (in_sizes[i] == CIN * CRD)          w_out = (const float*)d_in[i];
    }

    proj_tc_kernel<<<dim3(32, 3, 8), 256>>>(x, w_in);
    attn_bf16_kernel<<<dim3(32, 8), 256>>>();
    out_tc_kernel<<<dim3(32, 4, 8), 256>>>(x, w_out, (float*)d_out);
}

// round 10
// speedup vs baseline: 1.9113x; 1.0418x over previous
#include <cuda_runtime.h>
#include <cuda_bf16.h>
#include <cstdint>

// NonLocalBlock: B=8, C=512, H=W=64 -> N=4096, CR=128
//   proj  = w_in[384,512] @ x[b,512,4096] (tf32 TC) -> Q,K,G packed bf16x2
//   attn  = flash softmax(Q K^T) G        (bf16 TC) -> Y fp32
//   out   = x + w_out[512,128] @ Y^T      (tf32 TC) -> [b,512,4096]

#define BATCH 8
#define CIN   512
#define NTOK  4096
#define CRD   128
#define CPAIR 64          // CRD/2 bf16x2 pairs per token

// Q/K/G stored as bf16x2 pairs along c: [token][64] u32.  Y stays fp32.
__device__ uint32_t g_qp[(size_t)BATCH * NTOK * CPAIR];
__device__ uint32_t g_kp[(size_t)BATCH * NTOK * CPAIR];
__device__ uint32_t g_gp[(size_t)BATCH * NTOK * CPAIR];
__device__ float    g_y [(size_t)BATCH * NTOK * CRD];

// ---------------------------------------------------------------------------
// mma wrappers (validated fragment layouts).
// ---------------------------------------------------------------------------
__device__ __forceinline__ void mma_tf32(float d[4], const uint32_t a[4],
                                         uint32_t b0, uint32_t b1,
                                         const float c[4]) {
    asm volatile(
        "mma.sync.aligned.m16n8k8.row.col.f32.tf32.tf32.f32 "
        "{%0,%1,%2,%3}, {%4,%5,%6,%7}, {%8,%9}, {%10,%11,%12,%13};\n"
        : "=f"(d[0]), "=f"(d[1]), "=f"(d[2]), "=f"(d[3])
        : "r"(a[0]), "r"(a[1]), "r"(a[2]), "r"(a[3]),
          "r"(b0), "r"(b1),
          "f"(c[0]), "f"(c[1]), "f"(c[2]), "f"(c[3]));
}

__device__ __forceinline__ void mma_bf16(float d[4], const uint32_t a[4],
                                         uint32_t b0, uint32_t b1,
                                         const float c[4]) {
    asm volatile(
        "mma.sync.aligned.m16n8k16.row.col.f32.bf16.bf16.f32 "
        "{%0,%1,%2,%3}, {%4,%5,%6,%7}, {%8,%9}, {%10,%11,%12,%13};\n"
        : "=f"(d[0]), "=f"(d[1]), "=f"(d[2]), "=f"(d[3])
        : "r"(a[0]), "r"(a[1]), "r"(a[2]), "r"(a[3]),
          "r"(b0), "r"(b1),
          "f"(c[0]), "f"(c[1]), "f"(c[2]), "f"(c[3]));
}

__device__ __forceinline__ uint32_t packbf(float lo, float hi) {
    __nv_bfloat162 h = __floats2bfloat162_rn(lo, hi);  // lo -> low 16 bits
    return *reinterpret_cast<uint32_t*>(&h);
}

// ---------------------------------------------------------------------------
// Kernel 1: projection GEMM, tf32 TC, epilogue packs bf16x2 directly.
// ---------------------------------------------------------------------------
#define XS_S 136
#define WJ_S 36

__global__ __launch_bounds__(256) void proj_tc_kernel(const float* __restrict__ x,
                                                      const float* __restrict__ w_in) {
    __shared__ float Xs[32 * XS_S];
    __shared__ float Ws[128 * WJ_S];
    const int n0 = blockIdx.x * 128;
    const int j0 = blockIdx.y * 128;
    const int b  = blockIdx.z;
    const int tid  = threadIdx.x;
    const int w    = tid >> 5;
    const int lane = tid & 31;
    const int gp = lane >> 2, tg = lane & 3;
    const int wm = w & 3;
    const int wn = w >> 2;

    const float* xb = x + (size_t)b * CIN * NTOK + n0;
    const float* wb = w_in + (size_t)j0 * CIN;

    float acc[2][8][4];
#pragma unroll
    for (int mt = 0; mt < 2; mt++)
#pragma unroll
        for (int nt = 0; nt < 8; nt++)
#pragma unroll
            for (int e = 0; e < 4; e++) acc[mt][nt][e] = 0.f;

    for (int c0 = 0; c0 < CIN; c0 += 32) {
        __syncthreads();
#pragma unroll
        for (int i = 0; i < 4; i++) {
            int idx = i * 256 + tid;
            int r = idx >> 5, c4 = (idx & 31) << 2;
            *(float4*)&Xs[r * XS_S + c4] =
                *(const float4*)(xb + (size_t)(c0 + r) * NTOK + c4);
        }
#pragma unroll
        for (int i = 0; i < 4; i++) {
            int idx = i * 256 + tid;
            int j = idx >> 3, f4 = (idx & 7) << 2;
            *(float4*)&Ws[j * WJ_S + f4] =
                *(const float4*)(wb + (size_t)j * CIN + c0 + f4);
        }
        __syncthreads();

#pragma unroll
        for (int kk = 0; kk < 4; kk++) {
            uint32_t a[2][4];
#pragma unroll
            for (int mt = 0; mt < 2; mt++) {
                int m = wm * 32 + mt * 16;
                a[mt][0] = __float_as_uint(Xs[(kk * 8 + tg) * XS_S + m + gp]);
                a[mt][1] = __float_as_uint(Xs[(kk * 8 + tg) * XS_S + m + gp + 8]);
                a[mt][2] = __float_as_uint(Xs[(kk * 8 + tg + 4) * XS_S + m + gp]);
                a[mt][3] = __float_as_uint(Xs[(kk * 8 + tg + 4) * XS_S + m + gp + 8]);
            }
#pragma unroll
            for (int nt = 0; nt < 8; nt++) {
                int j = wn * 64 + nt * 8;
                uint32_t b0 = __float_as_uint(Ws[(j + gp) * WJ_S + kk * 8 + tg]);
                uint32_t b1 = __float_as_uint(Ws[(j + gp) * WJ_S + kk * 8 + tg + 4]);
                mma_tf32(acc[0][nt], a[0], b0, b1, acc[0][nt]);
                mma_tf32(acc[1][nt], a[1], b0, b1, acc[1][nt]);
            }
        }
    }

    // Epilogue: acc[..][0],[1] are adjacent c (2tg, 2tg+1) -> one bf16x2.
    uint32_t* dst = (j0 == 0) ? g_qp : (j0 == 128) ? g_kp : g_gp;
    uint32_t* base = dst + ((size_t)b * NTOK + n0 + wm * 32) * CPAIR + wn * 32;
#pragma unroll
    for (int mt = 0; mt < 2; mt++)
#pragma unroll
        for (int nt = 0; nt < 8; nt++) {
            base[(mt * 16 + gp) * CPAIR + nt * 4 + tg] =
                packbf(acc[mt][nt][0], acc[mt][nt][1]);
            base[(mt * 16 + gp + 8) * CPAIR + nt * 4 + tg] =
                packbf(acc[mt][nt][2], acc[mt][nt][3]);
        }
}

// ---------------------------------------------------------------------------
// Kernel 2: flash attention, bf16 m16n8k16.  Tiles arrive pre-packed:
//   K tile load = pure uint4 copy; G tile = uint4 + PRMT kv-interleave.
// smem: Ks32[64][68] (banks 4gp+tg), Gs32[32][136] (banks 8tg+gp).
// ---------------------------------------------------------------------------
#define KS32_S 68
#define GS32_S 136

__global__ __launch_bounds__(256, 1) void attn_bf16_kernel() {
    __shared__ uint32_t Ks32[64 * KS32_S];
    __shared__ uint32_t Gs32[32 * GS32_S];

    const int q0  = blockIdx.x * 128;
    const int b   = blockIdx.y;
    const int tid = threadIdx.x;
    const int w    = tid >> 5;
    const int lane = tid & 31;
    const int gp = lane >> 2;
    const int tg = lane & 3;

    // Q fragments: direct u32 loads of pre-packed pairs (pair idx = c/2).
    const uint32_t* Qg = g_qp + ((size_t)b * NTOK + q0 + w * 16) * CPAIR;
    uint32_t qf[8][4];
#pragma unroll
    for (int t = 0; t < 8; t++) {
        qf[t][0] = Qg[gp * CPAIR + t * 8 + tg];
        qf[t][1] = Qg[(gp + 8) * CPAIR + t * 8 + tg];
        qf[t][2] = Qg[gp * CPAIR + t * 8 + 4 + tg];
        qf[t][3] = Qg[(gp + 8) * CPAIR + t * 8 + 4 + tg];
    }

    float o[16][4];
#pragma unroll
    for (int j = 0; j < 16; j++)
#pragma unroll
        for (int e = 0; e < 4; e++) o[j][e] = 0.f;
    float m0 = -3.0e38f, m1 = -3.0e38f, l0 = 0.f, l1 = 0.f;

    const uint32_t* Kg = g_kp + (size_t)b * NTOK * CPAIR;
    const uint32_t* Gg = g_gp + (size_t)b * NTOK * CPAIR;

    for (int kt = 0; kt < NTOK / 64; kt++) {
        const uint32_t* Kt = Kg + (size_t)kt * 64 * CPAIR;
        const uint32_t* Gt = Gg + (size_t)kt * 64 * CPAIR;
        __syncthreads();   // previous tile's readers done

        // K tile: straight uint4 copy (64 rows x 64 pairs).
#pragma unroll
        for (int i = 0; i < 4; i++) {
            int idx = i * 256 + tid;               // 0..1023
            int r = idx >> 4, q4 = (idx & 15) << 2;
            *(uint4*)&Ks32[r * KS32_S + q4] = *(const uint4*)(Kt + r * CPAIR + q4);
        }
        // G tile: rows 2kp/2kp+1 c-pairs -> kv-pairs via PRMT.
        // {G[2kp][2cp],G[2kp][2cp+1]} + {G[2kp+1][2cp],G[2kp+1][2cp+1]}
        //   -> Gs32[kp][2cp] = {G[2kp][2cp],G[2kp+1][2cp]},  [2cp+1] likewise.
#pragma unroll
        for (int i = 0; i < 2; i++) {
            int idx = i * 256 + tid;               // 0..511
            int kp = idx >> 4, cpg = (idx & 15) << 2;
            uint4 A = *(const uint4*)(Gt + (2 * kp) * CPAIR + cpg);
            uint4 B = *(const uint4*)(Gt + (2 * kp + 1) * CPAIR + cpg);
            uint4 o0, o1;
            o0.x = __byte_perm(A.x, B.x, 0x5410); o0.y = __byte_perm(A.x, B.x, 0x7632);
            o0.z = __byte_perm(A.y, B.y, 0x5410); o0.w = __byte_perm(A.y, B.y, 0x7632);
            o1.x = __byte_perm(A.z, B.z, 0x5410); o1.y = __byte_perm(A.z, B.z, 0x7632);
            o1.z = __byte_perm(A.w, B.w, 0x5410); o1.w = __byte_perm(A.w, B.w, 0x7632);
            *(uint4*)&Gs32[kp * GS32_S + 2 * cpg]     = o0;
            *(uint4*)&Gs32[kp * GS32_S + 2 * cpg + 4] = o1;
        }
        __syncthreads();

        // GEMM1: S[16q x 64kv] = Q x K^T  (8 n-tiles, 8 k-steps of 16)
        float s[8][4];
#pragma unroll
        for (int j = 0; j < 8; j++)
#pragma unroll
            for (int e = 0; e < 4; e++) s[j][e] = 0.f;
#pragma unroll
        for (int t = 0; t < 8; t++) {
#pragma unroll
            for (int j = 0; j < 8; j++) {
                uint32_t b0 = Ks32[(j * 8 + gp) * KS32_S + t * 8 + tg];
                uint32_t b1 = Ks32[(j * 8 + gp) * KS32_S + t * 8 + tg + 4];
                mma_bf16(s[j], qf[t], b0, b1, s[j]);
            }
        }

        // Online softmax (rows gp / gp+8, each across a 4-lane quad).
        float mx0 = -3.0e38f, mx1 = -3.0e38f;
#pragma unroll
        for (int j = 0; j < 8; j++) {
            mx0 = fmaxf(mx0, fmaxf(s[j][0], s[j][1]));
            mx1 = fmaxf(mx1, fmaxf(s[j][2], s[j][3]));
        }
        mx0 = fmaxf(mx0, __shfl_xor_sync(0xffffffffu, mx0, 1));
        mx0 = fmaxf(mx0, __shfl_xor_sync(0xffffffffu, mx0, 2));
        mx1 = fmaxf(mx1, __shfl_xor_sync(0xffffffffu, mx1, 1));
        mx1 = fmaxf(mx1, __shfl_xor_sync(0xffffffffu, mx1, 2));
        float nm0 = fmaxf(m0, mx0), nm1 = fmaxf(m1, mx1);
        float corr0 = __expf(m0 - nm0), corr1 = __expf(m1 - nm1);
        m0 = nm0; m1 = nm1;
        float ps0 = 0.f, ps1 = 0.f;
#pragma unroll
        for (int j = 0; j < 8; j++) {
            s[j][0] = __expf(s[j][0] - nm0);
            s[j][1] = __expf(s[j][1] - nm0);
            s[j][2] = __expf(s[j][2] - nm1);
            s[j][3] = __expf(s[j][3] - nm1);
            ps0 += s[j][0] + s[j][1];
            ps1 += s[j][2] + s[j][3];
        }
        ps0 += __shfl_xor_sync(0xffffffffu, ps0, 1);
        ps0 += __shfl_xor_sync(0xffffffffu, ps0, 2);
        ps1 += __shfl_xor_sync(0xffffffffu, ps1, 1);
        ps1 += __shfl_xor_sync(0xffffffffu, ps1, 2);
        l0 = l0 * corr0 + ps0;
        l1 = l1 * corr1 + ps1;
#pragma unroll
        for (int j = 0; j < 16; j++) {
            o[j][0] *= corr0; o[j][1] *= corr0;
            o[j][2] *= corr1; o[j][3] *= corr1;
        }

        // Pack P into GEMM2 A-fragments in registers (C-frag == A-frag).
        uint32_t pe[8][2];
#pragma unroll
        for (int j = 0; j < 8; j++) {
            pe[j][0] = packbf(s[j][0], s[j][1]);   // row gp
            pe[j][1] = packbf(s[j][2], s[j][3]);   // row gp+8
        }

        // GEMM2: O[16q x 128c] += P x G  (4 k-steps of 16 kv, 16 n-tiles)
#pragma unroll
        for (int ss = 0; ss < 4; ss++) {
            uint32_t a[4] = {pe[2 * ss][0], pe[2 * ss][1],
                             pe[2 * ss + 1][0], pe[2 * ss + 1][1]};
#pragma unroll
            for (int j2 = 0; j2 < 16; j2++) {
                uint32_t b0 = Gs32[(ss * 8 + tg) * GS32_S + j2 * 8 + gp];
                uint32_t b1 = Gs32[(ss * 8 + tg + 4) * GS32_S + j2 * 8 + gp];
                mma_bf16(o[j2], a, b0, b1, o[j2]);
            }
        }
    }

    const float inv0 = 1.f / l0, inv1 = 1.f / l1;
    float* Yg = g_y + ((size_t)b * NTOK + q0 + w * 16) * CRD;
#pragma unroll
    for (int j2 = 0; j2 < 16; j2++) {
        *(float2*)&Yg[gp * CRD + j2 * 8 + 2 * tg] =
            make_float2(o[j2][0] * inv0, o[j2][1] * inv0);
        *(float2*)&Yg[(gp + 8) * CRD + j2 * 8 + 2 * tg] =
            make_float2(o[j2][2] * inv1, o[j2][3] * inv1);
    }
}

// ---------------------------------------------------------------------------
// Kernel 3: output GEMM + residual, tf32 TC (R5-validated).
// ---------------------------------------------------------------------------
#define OA_S 36

__global__ __launch_bounds__(256) void out_tc_kernel(const float* __restrict__ x,
                                                     const float* __restrict__ w_out,
                                                     float* __restrict__ out) {
    __shared__ float As[128 * OA_S];
    __shared__ float Bs[128 * OA_S];
    const int n0 = blockIdx.x * 128;
    const int c0 = blockIdx.y * 128;
    const int b  = blockIdx.z;
    const int tid  = threadIdx.x;
    const int w    = tid >> 5;
    const int lane = tid & 31;
    const int gp = lane >> 2, tg = lane & 3;
    const int wm = w & 3;
    const int wn = w >> 2;

    const float* Wg = w_out + (size_t)c0 * CRD;
    const float* Yg = g_y + ((size_t)b * NTOK + n0) * CRD;

    float acc[2][8][4];
#pragma unroll
    for (int mt = 0; mt < 2; mt++)
#pragma unroll
        for (int nt = 0; nt < 8; nt++)
#pragma unroll
            for (int e = 0; e < 4; e++) acc[mt][nt][e] = 0.f;

    for (int k0 = 0; k0 < CRD; k0 += 32) {
        __syncthreads();
#pragma unroll
        for (int i = 0; i < 4; i++) {
            int idx = i * 256 + tid;
            int r = idx >> 3, f4 = (idx & 7) << 2;
            *(float4*)&As[r * OA_S + f4] =
                *(const float4*)(Wg + (size_t)r * CRD + k0 + f4);
            *(float4*)&Bs[r * OA_S + f4] =
                *(const float4*)(Yg + (size_t)r * CRD + k0 + f4);
        }
        __syncthreads();

#pragma unroll
        for (int kk = 0; kk < 4; kk++) {
            uint32_t a[2][4];
#pragma unroll
            for (int mt = 0; mt < 2; mt++) {
                int c = wm * 32 + mt * 16;
                a[mt][0] = __float_as_uint(As[(c + gp) * OA_S + kk * 8 + tg]);
                a[mt][1] = __float_as_uint(As[(c + gp + 8) * OA_S + kk * 8 + tg]);
                a[mt][2] = __float_as_uint(As[(c + gp) * OA_S + kk * 8 + tg + 4]);
                a[mt][3] = __float_as_uint(As[(c + gp + 8) * OA_S + kk * 8 + tg + 4]);
            }
#pragma unroll
            for (int nt = 0; nt < 8; nt++) {
                int n = wn * 64 + nt * 8;
                uint32_t b0 = __float_as_uint(Bs[(n + gp) * OA_S + kk * 8 + tg]);
                uint32_t b1 = __float_as_uint(Bs[(n + gp) * OA_S + kk * 8 + tg + 4]);
                mma_tf32(acc[0][nt], a[0], b0, b1, acc[0][nt]);
                mma_tf32(acc[1][nt], a[1], b0, b1, acc[1][nt]);
            }
        }
    }

#pragma unroll
    for (int mt = 0; mt < 2; mt++)
#pragma unroll
        for (int nt = 0; nt < 8; nt++) {
            size_t r0 = ((size_t)b * CIN + c0 + wm * 32 + mt * 16 + gp) * NTOK
                        + n0 + wn * 64 + nt * 8 + 2 * tg;
            size_t r1 = r0 + (size_t)8 * NTOK;
            float2 x0 = *(const float2*)(x + r0);
            float2 x1 = *(const float2*)(x + r1);
            *(float2*)(out + r0) = make_float2(x0.x + acc[mt][nt][0],
                                               x0.y + acc[mt][nt][1]);
            *(float2*)(out + r1) = make_float2(x1.x + acc[mt][nt][2],
                                               x1.y + acc[mt][nt][3]);
        }
}

// ---------------------------------------------------------------------------
extern "C" void kernel_launch(void* const* d_in, const int* in_sizes, int n_in,
                              void* d_out, int out_size) {
    const float* x = nullptr; const float* w_in = nullptr; const float* w_out = nullptr;
    for (int i = 0; i < n_in; i++) {
        if (in_sizes[i] == BATCH * CIN * NTOK)      x     = (const float*)d_in[i];
        else if (in_sizes[i] == 3 * CRD * CIN)      w_in  = (const float*)d_in[i];
        else if (in_sizes[i] == CIN * CRD)          w_out = (const float*)d_in[i];
    }

    proj_tc_kernel<<<dim3(32, 3, 8), 256>>>(x, w_in);
    attn_bf16_kernel<<<dim3(32, 8), 256>>>();
    out_tc_kernel<<<dim3(32, 4, 8), 256>>>(x, w_out, (float*)d_out);
}